// round 10
// baseline (speedup 1.0000x reference)
#include <cuda_runtime.h>
#include <cuda_bf16.h>
#include <cuda_fp16.h>
#include <cstdint>

#define NN 50000
#define EE 800000
#define INF 128
#define HC 128
#define HH 8
#define ED 16

#define NPAD 50176            // 1024 * 49, >= NN+1
#define CHUNK 16              // sorted edges per warp
#define EG_ROWS 128           // edges per egemm CTA

// ---- scratch (device globals; no allocation allowed) ----
__device__ __align__(16) float g_q[NN * HC];
__device__ __align__(16) float g_k[NN * HC];
__device__ __align__(16) float g_v[NN * HC];
__device__ __align__(16) float g_attn[NN * HC];   // unnormalized numerator
__device__ __align__(16) float g_sum[NN * HH];    // softmax denominator
__device__ int g_cnt[NPAD];        // per-dst degree histogram (zero-padded)
__device__ int g_rowptr[NPAD];     // exclusive prefix sum
__device__ int g_wcnt[NN];         // write cursors for permute
__device__ __align__(16) int4 g_sde[EE];  // (src, dst, eid) sorted by dst

// bf16 hi/lo scratch
__device__ __align__(16) unsigned short g_xh[NPAD * INF];
__device__ __align__(16) unsigned short g_xl[NPAD * INF];
__device__ __align__(16) unsigned short g_wh[4][HC * INF];  // [n][k] layout
__device__ __align__(16) unsigned short g_wl[4][HC * INF];

// precomputed edge bias  e = edge_attr @ w_e, fp16 [E][128]
__device__ __align__(16) __half g_e[(size_t)EE * HC];

// ---------------------------------------------------------------------------
__global__ void zero_kernel() {
    int i = blockIdx.x * blockDim.x + threadIdx.x;
    if (i < NPAD) g_cnt[i] = 0;
    int n4 = (NN * HC) / 4;
    if (i < n4) ((float4*)g_attn)[i] = make_float4(0.f, 0.f, 0.f, 0.f);
    if (i < NN * HH) g_sum[i] = 0.f;
}

__global__ void hist_kernel(const int* __restrict__ ei) {
    int e = blockIdx.x * blockDim.x + threadIdx.x;
    if (e < EE) atomicAdd(&g_cnt[ei[EE + e]], 1);
}

// ---------------------------------------------------------------------------
// single-block exclusive scan of g_cnt[NPAD] -> g_rowptr (+ g_wcnt copy)
// 1024 threads x 49 elements (proven in R8)
// ---------------------------------------------------------------------------
__global__ __launch_bounds__(1024) void scan_kernel() {
    __shared__ int wsum[32];
    int t = threadIdx.x;
    int lane = t & 31, wid = t >> 5;
    int base = t * 49;

    int s = 0;
    #pragma unroll 7
    for (int i = 0; i < 49; i++) s += g_cnt[base + i];

    int ss = s;
    #pragma unroll
    for (int off = 1; off < 32; off <<= 1) {
        int u = __shfl_up_sync(0xffffffffu, ss, off);
        if (lane >= off) ss += u;
    }
    if (lane == 31) wsum[wid] = ss;
    __syncthreads();
    if (wid == 0) {
        int ws = wsum[lane];
        #pragma unroll
        for (int off = 1; off < 32; off <<= 1) {
            int u = __shfl_up_sync(0xffffffffu, ws, off);
            if (lane >= off) ws += u;
        }
        wsum[lane] = ws;
    }
    __syncthreads();

    int run = ss - s + (wid > 0 ? wsum[wid - 1] : 0);
    #pragma unroll 7
    for (int i = 0; i < 49; i++) {
        int idx = base + i;
        g_rowptr[idx] = run;
        if (idx < NN) g_wcnt[idx] = run;
        run += g_cnt[idx];
    }
}

__global__ void permute_kernel(const int* __restrict__ ei) {
    int e = blockIdx.x * blockDim.x + threadIdx.x;
    if (e < EE) {
        int src = ei[e];
        int dst = ei[EE + e];
        int pos = atomicAdd(&g_wcnt[dst], 1);
        g_sde[pos] = make_int4(src, dst, e, 0);
    }
}

// ---------------------------------------------------------------------------
// convert x (fp32 [m][k]) -> bf16 hi/lo, same layout
// ---------------------------------------------------------------------------
__global__ void convert_x_kernel(const float* __restrict__ x) {
    int i = blockIdx.x * blockDim.x + threadIdx.x;   // float4 index
    if (i >= (NN * INF) / 4) return;
    float4 v = ((const float4*)x)[i];
    float vv[4] = {v.x, v.y, v.z, v.w};
    unsigned short h[4], l[4];
    #pragma unroll
    for (int j = 0; j < 4; j++) {
        __nv_bfloat16 hb = __float2bfloat16(vv[j]);
        __nv_bfloat16 lb = __float2bfloat16(vv[j] - __bfloat162float(hb));
        h[j] = __bfloat16_as_ushort(hb);
        l[j] = __bfloat16_as_ushort(lb);
    }
    uint2 ph = make_uint2((uint32_t)h[0] | ((uint32_t)h[1] << 16),
                          (uint32_t)h[2] | ((uint32_t)h[3] << 16));
    uint2 pl = make_uint2((uint32_t)l[0] | ((uint32_t)l[1] << 16),
                          (uint32_t)l[2] | ((uint32_t)l[3] << 16));
    ((uint2*)g_xh)[i] = ph;
    ((uint2*)g_xl)[i] = pl;
}

// ---------------------------------------------------------------------------
// convert W (fp32 [k][n]) -> bf16 hi/lo, TRANSPOSED to [n][k]
// ---------------------------------------------------------------------------
__global__ void convert_w_kernel(
    const float* __restrict__ wq, const float* __restrict__ wk,
    const float* __restrict__ wv, const float* __restrict__ ws)
{
    int m = blockIdx.y;
    const float* W = (m == 0) ? wq : (m == 1) ? wk : (m == 2) ? wv : ws;
    int idx = blockIdx.x * 256 + threadIdx.x;  // 0..16383
    int n = idx & 127, k = idx >> 7;
    float v = W[k * HC + n];
    __nv_bfloat16 hb = __float2bfloat16(v);
    __nv_bfloat16 lb = __float2bfloat16(v - __bfloat162float(hb));
    g_wh[m][n * INF + k] = __bfloat16_as_ushort(hb);
    g_wl[m][n * INF + k] = __bfloat16_as_ushort(lb);
}

// ---------------------------------------------------------------------------
// HMMA GEMM: D = x@W + b for 4 matrices, bf16 hi/lo split (3 terms).
// CTA = 128x128 tile, 8 warps (2x4), warp tile 64x32, m16n8k16 atoms.
// ---------------------------------------------------------------------------
#define ASTRIDE 272          // bytes per smem row (136 bf16)
#define SM_A_H  0            // 128*272 = 34816
#define SM_A_L  34816
#define SM_B_H  69632
#define SM_B_L  104448
#define SM_BIAS 139264       // 512 floats = 2048
#define SM_TOT  141312

__global__ __launch_bounds__(256, 1) void mma_gemm_kernel(
    const float* __restrict__ bq, const float* __restrict__ bk,
    const float* __restrict__ bv, const float* __restrict__ bs,
    float* __restrict__ out)
{
    extern __shared__ char sm[];
    int tid = threadIdx.x;
    int w = tid >> 5;
    int lane = tid & 31;
    int g = lane >> 2;        // 0..7
    int t = lane & 3;         // 0..3
    int mw = w >> 2;          // 0..1
    int nw = w & 3;           // 0..3
    int rowBase = blockIdx.x * 128;

    #pragma unroll
    for (int i = 0; i < 8; i++) {
        int idx = tid + i * 256;          // 0..2047
        int r = idx >> 4;                 // row 0..127
        int kc = idx & 15;                // 8-bf16 chunk
        size_t src = ((size_t)(rowBase + r) * INF + kc * 8) * 2;
        *(uint4*)(sm + SM_A_H + r * ASTRIDE + kc * 16) =
            *(const uint4*)((const char*)g_xh + src);
        *(uint4*)(sm + SM_A_L + r * ASTRIDE + kc * 16) =
            *(const uint4*)((const char*)g_xl + src);
    }
    for (int j = tid; j < 512; j += 256) {
        int m = j >> 7, c = j & 127;
        const float* B = (m == 0) ? bq : (m == 1) ? bk : (m == 2) ? bv : bs;
        *(float*)(sm + SM_BIAS + j * 4) = B[c];
    }

    for (int m = 0; m < 4; m++) {
        __syncthreads();
        #pragma unroll
        for (int i = 0; i < 8; i++) {
            int idx = tid + i * 256;
            int n = idx >> 4;
            int kc = idx & 15;
            size_t src = ((size_t)n * INF + kc * 8) * 2;
            *(uint4*)(sm + SM_B_H + n * ASTRIDE + kc * 16) =
                *(const uint4*)((const char*)g_wh[m] + src);
            *(uint4*)(sm + SM_B_L + n * ASTRIDE + kc * 16) =
                *(const uint4*)((const char*)g_wl[m] + src);
        }
        __syncthreads();

        float acc[4][4][4];
        #pragma unroll
        for (int a = 0; a < 4; a++)
            #pragma unroll
            for (int b = 0; b < 4; b++)
                #pragma unroll
                for (int c = 0; c < 4; c++) acc[a][b][c] = 0.f;

        #pragma unroll
        for (int s = 0; s < 3; s++) {
            const char* Ab = sm + ((s == 2) ? SM_A_L : SM_A_H);
            const char* Bb = sm + ((s == 1) ? SM_B_L : SM_B_H);
            #pragma unroll
            for (int kt = 0; kt < 8; kt++) {
                int kb = (kt * 16 + t * 2) * 2;
                uint32_t bf[4][2];
                #pragma unroll
                for (int nt = 0; nt < 4; nt++) {
                    const char* p = Bb + (nw * 32 + nt * 8 + g) * ASTRIDE + kb;
                    bf[nt][0] = *(const uint32_t*)p;
                    bf[nt][1] = *(const uint32_t*)(p + 16);
                }
                #pragma unroll
                for (int mt = 0; mt < 4; mt++) {
                    const char* p = Ab + (mw * 64 + mt * 16 + g) * ASTRIDE + kb;
                    uint32_t a0 = *(const uint32_t*)p;
                    uint32_t a1 = *(const uint32_t*)(p + 8 * ASTRIDE);
                    uint32_t a2 = *(const uint32_t*)(p + 16);
                    uint32_t a3 = *(const uint32_t*)(p + 8 * ASTRIDE + 16);
                    #pragma unroll
                    for (int nt = 0; nt < 4; nt++) {
                        asm volatile(
                            "mma.sync.aligned.m16n8k16.row.col.f32.bf16.bf16.f32 "
                            "{%0,%1,%2,%3}, {%4,%5,%6,%7}, {%8,%9}, {%0,%1,%2,%3};"
                            : "+f"(acc[mt][nt][0]), "+f"(acc[mt][nt][1]),
                              "+f"(acc[mt][nt][2]), "+f"(acc[mt][nt][3])
                            : "r"(a0), "r"(a1), "r"(a2), "r"(a3),
                              "r"(bf[nt][0]), "r"(bf[nt][1]));
                    }
                }
            }
        }

        float* O = (m == 0) ? g_q : (m == 1) ? g_k : (m == 2) ? g_v : out;
        const float* sb = (const float*)(sm + SM_BIAS) + m * 128;
        #pragma unroll
        for (int mt = 0; mt < 4; mt++) {
            int r0 = rowBase + mw * 64 + mt * 16 + g;
            int r1 = r0 + 8;
            #pragma unroll
            for (int nt = 0; nt < 4; nt++) {
                int col = nw * 32 + nt * 8 + t * 2;
                float bx = sb[col], by = sb[col + 1];
                if (r0 < NN) {
                    float2 o0 = make_float2(acc[mt][nt][0] + bx,
                                            acc[mt][nt][1] + by);
                    *(float2*)&O[(size_t)r0 * HC + col] = o0;
                }
                if (r1 < NN) {
                    float2 o1 = make_float2(acc[mt][nt][2] + bx,
                                            acc[mt][nt][3] + by);
                    *(float2*)&O[(size_t)r1 * HC + col] = o1;
                }
            }
        }
    }
}

// ---------------------------------------------------------------------------
// egemm: E = edge_attr @ w_e -> g_e (fp16 [E][128]).
// ---------------------------------------------------------------------------
__global__ __launch_bounds__(256) void egemm_kernel(
    const float* __restrict__ ea, const float* __restrict__ we)
{
    __shared__ unsigned short Ah[EG_ROWS * 16], Al[EG_ROWS * 16];
    __shared__ unsigned short Bh[HC * 16], Bl[HC * 16];

    int tid = threadIdx.x;
    int e0 = blockIdx.x * EG_ROWS;

    {
        int r = tid >> 1, half = (tid & 1) * 8;
        int ge = e0 + r;
        float4 v0, v1;
        if (ge < EE) {
            v0 = *(const float4*)&ea[(size_t)ge * ED + half];
            v1 = *(const float4*)&ea[(size_t)ge * ED + half + 4];
        } else {
            v0 = v1 = make_float4(0.f, 0.f, 0.f, 0.f);
        }
        float vv[8] = {v0.x, v0.y, v0.z, v0.w, v1.x, v1.y, v1.z, v1.w};
        #pragma unroll
        for (int j = 0; j < 8; j++) {
            __nv_bfloat16 hb = __float2bfloat16(vv[j]);
            __nv_bfloat16 lb = __float2bfloat16(vv[j] - __bfloat162float(hb));
            Ah[r * 16 + half + j] = __bfloat16_as_ushort(hb);
            Al[r * 16 + half + j] = __bfloat16_as_ushort(lb);
        }
    }
    {
        int k = tid >> 4, n0 = (tid & 15) * 8;
        #pragma unroll
        for (int j = 0; j < 8; j++) {
            float v = we[k * HC + n0 + j];
            __nv_bfloat16 hb = __float2bfloat16(v);
            __nv_bfloat16 lb = __float2bfloat16(v - __bfloat162float(hb));
            Bh[(n0 + j) * 16 + k] = __bfloat16_as_ushort(hb);
            Bl[(n0 + j) * 16 + k] = __bfloat16_as_ushort(lb);
        }
    }
    __syncthreads();

    int w = tid >> 5, lane = tid & 31;
    int g = lane >> 2, t = lane & 3;
    int mw = w >> 1, nw = w & 1;

    float acc[2][8][4];
    #pragma unroll
    for (int a = 0; a < 2; a++)
        #pragma unroll
        for (int b = 0; b < 8; b++)
            #pragma unroll
            for (int c = 0; c < 4; c++) acc[a][b][c] = 0.f;

    #pragma unroll
    for (int s = 0; s < 3; s++) {
        const unsigned short* A = (s == 2) ? Al : Ah;
        const unsigned short* B = (s == 1) ? Bl : Bh;
        uint32_t bf[8][2];
        #pragma unroll
        for (int nt = 0; nt < 8; nt++) {
            const unsigned short* p = &B[(nw * 64 + nt * 8 + g) * 16 + t * 2];
            bf[nt][0] = *(const uint32_t*)p;
            bf[nt][1] = *(const uint32_t*)(p + 8);
        }
        #pragma unroll
        for (int mt = 0; mt < 2; mt++) {
            const unsigned short* p = &A[(mw * 32 + mt * 16 + g) * 16 + t * 2];
            uint32_t a0 = *(const uint32_t*)p;
            uint32_t a1 = *(const uint32_t*)(p + 8 * 16);
            uint32_t a2 = *(const uint32_t*)(p + 8);
            uint32_t a3 = *(const uint32_t*)(p + 8 * 16 + 8);
            #pragma unroll
            for (int nt = 0; nt < 8; nt++) {
                asm volatile(
                    "mma.sync.aligned.m16n8k16.row.col.f32.bf16.bf16.f32 "
                    "{%0,%1,%2,%3}, {%4,%5,%6,%7}, {%8,%9}, {%0,%1,%2,%3};"
                    : "+f"(acc[mt][nt][0]), "+f"(acc[mt][nt][1]),
                      "+f"(acc[mt][nt][2]), "+f"(acc[mt][nt][3])
                    : "r"(a0), "r"(a1), "r"(a2), "r"(a3),
                      "r"(bf[nt][0]), "r"(bf[nt][1]));
            }
        }
    }

    #pragma unroll
    for (int mt = 0; mt < 2; mt++) {
        int r0 = e0 + mw * 32 + mt * 16 + g;
        int r1 = r0 + 8;
        #pragma unroll
        for (int nt = 0; nt < 8; nt++) {
            int col = nw * 64 + nt * 8 + t * 2;
            if (r0 < EE) {
                __half2 h0 = __floats2half2_rn(acc[mt][nt][0], acc[mt][nt][1]);
                *(__half2*)&g_e[(size_t)r0 * HC + col] = h0;
            }
            if (r1 < EE) {
                __half2 h1 = __floats2half2_rn(acc[mt][nt][2], acc[mt][nt][3]);
                *(__half2*)&g_e[(size_t)r1 * HC + col] = h1;
            }
        }
    }
}

// ---------------------------------------------------------------------------
// Sorted-scatter edge kernel, software-pipelined: prefetch iteration i+1's
// sde/e/k/v before processing iteration i (hides L2 gather latency).
// ---------------------------------------------------------------------------
__global__ __launch_bounds__(256) void edge_sorted_kernel()
{
    int lane = threadIdx.x & 31;
    int w = (blockIdx.x * 256 + threadIdx.x) >> 5;
    int base = w * CHUNK;
    if (base >= EE) return;
    int end = (base + CHUNK < EE) ? base + CHUNK : EE;

    int c0 = lane << 2;
    int head = lane >> 2;

    // pipeline stage 0 loads
    int4 sde0 = g_sde[base];
    uint2 eu0 = *(const uint2*)&g_e[(size_t)sde0.z * HC + c0];
    float4 k0 = *(const float4*)&g_k[(size_t)sde0.x * HC + c0];
    float4 v0 = *(const float4*)&g_v[(size_t)sde0.x * HC + c0];

    int cur_dst = -1;
    float4 q4 = make_float4(0.f, 0.f, 0.f, 0.f);
    float nx = 0.f, ny = 0.f, nz = 0.f, nw4 = 0.f, den = 0.f;

    for (int i = base; i < end; i++) {
        // prefetch next iteration
        int4 sde1; uint2 eu1; float4 k1, v1;
        bool more = (i + 1 < end);
        if (more) {
            sde1 = g_sde[i + 1];
            eu1 = *(const uint2*)&g_e[(size_t)sde1.z * HC + c0];
            k1 = *(const float4*)&g_k[(size_t)sde1.x * HC + c0];
            v1 = *(const float4*)&g_v[(size_t)sde1.x * HC + c0];
        }

        int dst = sde0.y;
        if (dst != cur_dst) {
            if (cur_dst >= 0) {
                float* op = g_attn + (size_t)cur_dst * HC + c0;
                asm volatile("red.global.add.v4.f32 [%0], {%1, %2, %3, %4};"
                             :: "l"(op), "f"(nx), "f"(ny), "f"(nz), "f"(nw4)
                             : "memory");
                if ((lane & 3) == 0) {
                    float* dp = &g_sum[cur_dst * HH + head];
                    asm volatile("red.global.add.f32 [%0], %1;"
                                 :: "l"(dp), "f"(den) : "memory");
                }
            }
            cur_dst = dst;
            q4 = *(const float4*)&g_q[(size_t)dst * HC + c0];
            nx = ny = nz = nw4 = den = 0.f;
        }

        float2 f01 = __half22float2(*reinterpret_cast<__half2*>(&eu0.x));
        float2 f23 = __half22float2(*reinterpret_cast<__half2*>(&eu0.y));
        float ex = f01.x, ey = f01.y, ez = f23.x, ew = f23.y;

        float s = q4.x * (k0.x + ex) + q4.y * (k0.y + ey)
                + q4.z * (k0.z + ez) + q4.w * (k0.w + ew);
        s += __shfl_xor_sync(0xffffffffu, s, 1);
        s += __shfl_xor_sync(0xffffffffu, s, 2);

        float p = __expf(s * 0.25f);

        nx  += (v0.x + ex) * p;
        ny  += (v0.y + ey) * p;
        nz  += (v0.z + ez) * p;
        nw4 += (v0.w + ew) * p;
        den += p;

        if (more) { sde0 = sde1; eu0 = eu1; k0 = k1; v0 = v1; }
    }

    if (cur_dst >= 0) {
        float* op = g_attn + (size_t)cur_dst * HC + c0;
        asm volatile("red.global.add.v4.f32 [%0], {%1, %2, %3, %4};"
                     :: "l"(op), "f"(nx), "f"(ny), "f"(nz), "f"(nw4)
                     : "memory");
        if ((lane & 3) == 0) {
            float* dp = &g_sum[cur_dst * HH + head];
            asm volatile("red.global.add.f32 [%0], %1;"
                         :: "l"(dp), "f"(den) : "memory");
        }
    }
}

// ---------------------------------------------------------------------------
__global__ __launch_bounds__(256) void normalize_kernel(float* __restrict__ out)
{
    int i = blockIdx.x * blockDim.x + threadIdx.x;
    int n4 = (NN * HC) / 4;
    if (i >= n4) return;
    int node = i >> 5;
    int head = (i & 31) >> 2;
    float inv = 1.f / (g_sum[node * HH + head] + 1e-16f);
    float4 a = ((const float4*)g_attn)[i];
    float4 o = ((float4*)out)[i];
    o.x += a.x * inv; o.y += a.y * inv;
    o.z += a.z * inv; o.w += a.w * inv;
    ((float4*)out)[i] = o;
}

// ---------------------------------------------------------------------------
extern "C" void kernel_launch(void* const* d_in, const int* in_sizes, int n_in,
                              void* d_out, int out_size)
{
    const float* x  = (const float*)d_in[0];
    const int*   ei = (const int*)d_in[1];
    const float* ea = (const float*)d_in[2];
    const float* wq = (const float*)d_in[3];
    const float* bq = (const float*)d_in[4];
    const float* wk = (const float*)d_in[5];
    const float* bk = (const float*)d_in[6];
    const float* wv = (const float*)d_in[7];
    const float* bv = (const float*)d_in[8];
    const float* we = (const float*)d_in[9];
    const float* ws = (const float*)d_in[10];
    const float* bs = (const float*)d_in[11];
    float* out = (float*)d_out;

    static bool attr_set = false;
    if (!attr_set) {
        cudaFuncSetAttribute(mma_gemm_kernel,
                             cudaFuncAttributeMaxDynamicSharedMemorySize, SM_TOT);
        attr_set = true;
    }

    // order chosen so the 4th launch (= ncu's captured slot) is mma_gemm
    zero_kernel<<<((NN * HC) / 4 + 255) / 256, 256>>>();
    convert_x_kernel<<<((NN * INF) / 4 + 255) / 256, 256>>>(x);
    dim3 gw(64, 4);
    convert_w_kernel<<<gw, 256>>>(wq, wk, wv, ws);
    mma_gemm_kernel<<<391, 256, SM_TOT>>>(bq, bk, bv, bs, out);   // 4th: profiled

    hist_kernel<<<(EE + 255) / 256, 256>>>(ei);
    scan_kernel<<<1, 1024>>>();
    permute_kernel<<<(EE + 255) / 256, 256>>>(ei);

    egemm_kernel<<<(EE + EG_ROWS - 1) / EG_ROWS, 256>>>(ea, we);

    int warps = (EE + CHUNK - 1) / CHUNK;
    edge_sorted_kernel<<<(warps * 32 + 255) / 256, 256>>>();

    normalize_kernel<<<((NN * HC) / 4 + 255) / 256, 256>>>(out);
}

// round 11
// speedup vs baseline: 1.1612x; 1.1612x over previous
#include <cuda_runtime.h>
#include <cuda_bf16.h>
#include <cuda_fp16.h>
#include <cstdint>

#define NN 50000
#define EE 800000
#define INF 128
#define HC 128
#define HH 8
#define ED 16

#define NPAD 50176            // 196 * 256, >= NN+1
#define CHUNK 16              // sorted edges per warp
#define EG_ROWS 128           // edges per egemm CTA

// ---- scratch (device globals; no allocation allowed) ----
__device__ __align__(16) float g_q[NN * HC];
__device__ __align__(16) float g_k[NN * HC];
__device__ __align__(16) float g_v[NN * HC];
__device__ __align__(16) float g_attn[NN * HC];   // unnormalized numerator
__device__ __align__(16) float g_sum[NN * HH];    // softmax denominator
__device__ int g_cnt[NPAD];        // per-dst degree histogram (zero-padded)
__device__ int g_rowptr[NPAD];     // exclusive prefix sum
__device__ int g_wcnt[NN];         // write cursors for permute
__device__ int g_blk[256];         // per-block sums for scan
__device__ __align__(16) int4 g_sde[EE];  // (src, dst, eid) sorted by dst

// bf16 hi/lo scratch
__device__ __align__(16) unsigned short g_xh[NPAD * INF];
__device__ __align__(16) unsigned short g_xl[NPAD * INF];
__device__ __align__(16) unsigned short g_wh[4][HC * INF];  // [n][k] layout
__device__ __align__(16) unsigned short g_wl[4][HC * INF];

// precomputed edge bias  e = edge_attr @ w_e, fp16 [E][128]
__device__ __align__(16) __half g_e[(size_t)EE * HC];

// ---------------------------------------------------------------------------
__device__ __forceinline__ void ldsm_x4(uint32_t& r0, uint32_t& r1,
                                        uint32_t& r2, uint32_t& r3,
                                        uint32_t saddr) {
    asm volatile("ldmatrix.sync.aligned.m8n8.x4.shared.b16 {%0,%1,%2,%3}, [%4];"
                 : "=r"(r0), "=r"(r1), "=r"(r2), "=r"(r3) : "r"(saddr));
}

// ---------------------------------------------------------------------------
__global__ void zero_kernel() {
    int i = blockIdx.x * blockDim.x + threadIdx.x;
    if (i < NPAD) g_cnt[i] = 0;
    int n4 = (NN * HC) / 4;
    if (i < n4) ((float4*)g_attn)[i] = make_float4(0.f, 0.f, 0.f, 0.f);
    if (i < NN * HH) g_sum[i] = 0.f;
}

__global__ void hist_kernel(const int* __restrict__ ei) {
    int e = blockIdx.x * blockDim.x + threadIdx.x;
    if (e < EE) atomicAdd(&g_cnt[ei[EE + e]], 1);
}

__global__ void scan1_kernel() {
    __shared__ int s[256];
    int t = threadIdx.x;
    int i = blockIdx.x * 256 + t;
    int v = g_cnt[i];
    s[t] = v;
    __syncthreads();
    #pragma unroll
    for (int off = 1; off < 256; off <<= 1) {
        int u = (t >= off) ? s[t - off] : 0;
        __syncthreads();
        s[t] += u;
        __syncthreads();
    }
    g_rowptr[i] = s[t] - v;
    if (t == 255) g_blk[blockIdx.x] = s[255];
}

__global__ void scan2_kernel() {
    __shared__ int s[256];
    int t = threadIdx.x;
    int v = (t < 196) ? g_blk[t] : 0;
    s[t] = v;
    __syncthreads();
    #pragma unroll
    for (int off = 1; off < 256; off <<= 1) {
        int u = (t >= off) ? s[t - off] : 0;
        __syncthreads();
        s[t] += u;
        __syncthreads();
    }
    if (t < 196) g_blk[t] = s[t] - v;
}

__global__ void scan3_kernel() {
    int i = blockIdx.x * blockDim.x + threadIdx.x;
    if (i < NPAD) {
        int v = g_rowptr[i] + g_blk[i >> 8];
        g_rowptr[i] = v;
        if (i < NN) g_wcnt[i] = v;
    }
}

__global__ void permute_kernel(const int* __restrict__ ei) {
    int e = blockIdx.x * blockDim.x + threadIdx.x;
    if (e < EE) {
        int src = ei[e];
        int dst = ei[EE + e];
        int pos = atomicAdd(&g_wcnt[dst], 1);
        g_sde[pos] = make_int4(src, dst, e, 0);
    }
}

// ---------------------------------------------------------------------------
// convert x (fp32 [m][k]) -> bf16 hi/lo, same layout
// ---------------------------------------------------------------------------
__global__ void convert_x_kernel(const float* __restrict__ x) {
    int i = blockIdx.x * blockDim.x + threadIdx.x;   // float4 index
    if (i >= (NN * INF) / 4) return;
    float4 v = ((const float4*)x)[i];
    float vv[4] = {v.x, v.y, v.z, v.w};
    unsigned short h[4], l[4];
    #pragma unroll
    for (int j = 0; j < 4; j++) {
        __nv_bfloat16 hb = __float2bfloat16(vv[j]);
        __nv_bfloat16 lb = __float2bfloat16(vv[j] - __bfloat162float(hb));
        h[j] = __bfloat16_as_ushort(hb);
        l[j] = __bfloat16_as_ushort(lb);
    }
    uint2 ph = make_uint2((uint32_t)h[0] | ((uint32_t)h[1] << 16),
                          (uint32_t)h[2] | ((uint32_t)h[3] << 16));
    uint2 pl = make_uint2((uint32_t)l[0] | ((uint32_t)l[1] << 16),
                          (uint32_t)l[2] | ((uint32_t)l[3] << 16));
    ((uint2*)g_xh)[i] = ph;
    ((uint2*)g_xl)[i] = pl;
}

// ---------------------------------------------------------------------------
// convert W (fp32 [k][n]) -> bf16 hi/lo, TRANSPOSED to [n][k]
// ---------------------------------------------------------------------------
__global__ void convert_w_kernel(
    const float* __restrict__ wq, const float* __restrict__ wk,
    const float* __restrict__ wv, const float* __restrict__ ws)
{
    int m = blockIdx.y;
    const float* W = (m == 0) ? wq : (m == 1) ? wk : (m == 2) ? wv : ws;
    int idx = blockIdx.x * 256 + threadIdx.x;  // 0..16383
    int n = idx & 127, k = idx >> 7;
    float v = W[k * HC + n];
    __nv_bfloat16 hb = __float2bfloat16(v);
    __nv_bfloat16 lb = __float2bfloat16(v - __bfloat162float(hb));
    g_wh[m][n * INF + k] = __bfloat16_as_ushort(hb);
    g_wl[m][n * INF + k] = __bfloat16_as_ushort(lb);
}

// ---------------------------------------------------------------------------
// HMMA GEMM: D = x@W + b for 4 matrices, bf16 hi/lo split (3 terms).
// CTA = 128x128 tile, 8 warps (2x4), warp tile 64x32, m16n8k16 atoms.
// Fragment loads via ldmatrix.x4 (6 LDSM/kt vs 24 LDS.32) — smem-port fix.
// ---------------------------------------------------------------------------
#define ASTRIDE 272          // bytes per smem row (136 bf16)
#define SM_A_H  0            // 128*272 = 34816
#define SM_A_L  34816
#define SM_B_H  69632
#define SM_B_L  104448
#define SM_BIAS 139264       // 512 floats = 2048
#define SM_TOT  141312

__global__ __launch_bounds__(256, 1) void mma_gemm_kernel(
    const float* __restrict__ bq, const float* __restrict__ bk,
    const float* __restrict__ bv, const float* __restrict__ bs,
    float* __restrict__ out)
{
    extern __shared__ char sm[];
    int tid = threadIdx.x;
    int w = tid >> 5;
    int lane = tid & 31;
    int g = lane >> 2;        // 0..7
    int t = lane & 3;         // 0..3
    int mw = w >> 2;          // 0..1
    int nw = w & 3;           // 0..3
    int rowBase = blockIdx.x * 128;

    // ---- copy A tile (hi+lo) from bf16 scratch (pad rows are zero) ----
    #pragma unroll
    for (int i = 0; i < 8; i++) {
        int idx = tid + i * 256;          // 0..2047
        int r = idx >> 4;                 // row 0..127
        int kc = idx & 15;                // 8-bf16 chunk
        size_t src = ((size_t)(rowBase + r) * INF + kc * 8) * 2;
        *(uint4*)(sm + SM_A_H + r * ASTRIDE + kc * 16) =
            *(const uint4*)((const char*)g_xh + src);
        *(uint4*)(sm + SM_A_L + r * ASTRIDE + kc * 16) =
            *(const uint4*)((const char*)g_xl + src);
    }
    for (int j = tid; j < 512; j += 256) {
        int m = j >> 7, c = j & 127;
        const float* B = (m == 0) ? bq : (m == 1) ? bk : (m == 2) ? bv : bs;
        *(float*)(sm + SM_BIAS + j * 4) = B[c];
    }

    uint32_t smBase = (uint32_t)__cvta_generic_to_shared(sm);
    int lrow = lane & 15;
    int khalf = lane >> 4;
    uint32_t aRowOff = (uint32_t)(mw * 64 + lrow) * ASTRIDE + khalf * 16;
    uint32_t bRowOff = (uint32_t)(nw * 32 + lrow) * ASTRIDE + khalf * 16;

    for (int m = 0; m < 4; m++) {
        __syncthreads();     // protect previous B from overwrite
        #pragma unroll
        for (int i = 0; i < 8; i++) {
            int idx = tid + i * 256;
            int n = idx >> 4;
            int kc = idx & 15;
            size_t src = ((size_t)n * INF + kc * 8) * 2;
            *(uint4*)(sm + SM_B_H + n * ASTRIDE + kc * 16) =
                *(const uint4*)((const char*)g_wh[m] + src);
            *(uint4*)(sm + SM_B_L + n * ASTRIDE + kc * 16) =
                *(const uint4*)((const char*)g_wl[m] + src);
        }
        __syncthreads();

        float acc[4][4][4];
        #pragma unroll
        for (int a = 0; a < 4; a++)
            #pragma unroll
            for (int b = 0; b < 4; b++)
                #pragma unroll
                for (int c = 0; c < 4; c++) acc[a][b][c] = 0.f;

        #pragma unroll
        for (int s = 0; s < 3; s++) {
            uint32_t aBase = smBase + ((s == 2) ? SM_A_L : SM_A_H) + aRowOff;
            uint32_t bBase = smBase + ((s == 1) ? SM_B_L : SM_B_H) + bRowOff;
            #pragma unroll
            for (int kt = 0; kt < 8; kt++) {
                uint32_t kOff = kt * 32;
                // B fragments: 2 x ldmatrix.x4 -> bf[nt][0/1] for nt 0..3
                uint32_t bf[4][2];
                ldsm_x4(bf[0][0], bf[1][0], bf[0][1], bf[1][1], bBase + kOff);
                ldsm_x4(bf[2][0], bf[3][0], bf[2][1], bf[3][1],
                        bBase + 16 * ASTRIDE + kOff);
                #pragma unroll
                for (int mt = 0; mt < 4; mt++) {
                    uint32_t a0, a1, a2, a3;
                    ldsm_x4(a0, a1, a2, a3,
                            aBase + (uint32_t)mt * 16 * ASTRIDE + kOff);
                    #pragma unroll
                    for (int nt = 0; nt < 4; nt++) {
                        asm volatile(
                            "mma.sync.aligned.m16n8k16.row.col.f32.bf16.bf16.f32 "
                            "{%0,%1,%2,%3}, {%4,%5,%6,%7}, {%8,%9}, {%0,%1,%2,%3};"
                            : "+f"(acc[mt][nt][0]), "+f"(acc[mt][nt][1]),
                              "+f"(acc[mt][nt][2]), "+f"(acc[mt][nt][3])
                            : "r"(a0), "r"(a1), "r"(a2), "r"(a3),
                              "r"(bf[nt][0]), "r"(bf[nt][1]));
                    }
                }
            }
        }

        float* O = (m == 0) ? g_q : (m == 1) ? g_k : (m == 2) ? g_v : out;
        const float* sb = (const float*)(sm + SM_BIAS) + m * 128;
        #pragma unroll
        for (int mt = 0; mt < 4; mt++) {
            int r0 = rowBase + mw * 64 + mt * 16 + g;
            int r1 = r0 + 8;
            #pragma unroll
            for (int nt = 0; nt < 4; nt++) {
                int col = nw * 32 + nt * 8 + t * 2;
                float bx = sb[col], by = sb[col + 1];
                if (r0 < NN) {
                    float2 o0 = make_float2(acc[mt][nt][0] + bx,
                                            acc[mt][nt][1] + by);
                    *(float2*)&O[(size_t)r0 * HC + col] = o0;
                }
                if (r1 < NN) {
                    float2 o1 = make_float2(acc[mt][nt][2] + bx,
                                            acc[mt][nt][3] + by);
                    *(float2*)&O[(size_t)r1 * HC + col] = o1;
                }
            }
        }
    }
}

// ---------------------------------------------------------------------------
// egemm: E = edge_attr @ w_e -> g_e (fp16 [E][128]).
// ---------------------------------------------------------------------------
__global__ __launch_bounds__(256) void egemm_kernel(
    const float* __restrict__ ea, const float* __restrict__ we)
{
    __shared__ unsigned short Ah[EG_ROWS * 16], Al[EG_ROWS * 16];
    __shared__ unsigned short Bh[HC * 16], Bl[HC * 16];

    int tid = threadIdx.x;
    int e0 = blockIdx.x * EG_ROWS;

    {
        int r = tid >> 1, half = (tid & 1) * 8;
        int ge = e0 + r;
        float4 v0, v1;
        if (ge < EE) {
            v0 = *(const float4*)&ea[(size_t)ge * ED + half];
            v1 = *(const float4*)&ea[(size_t)ge * ED + half + 4];
        } else {
            v0 = v1 = make_float4(0.f, 0.f, 0.f, 0.f);
        }
        float vv[8] = {v0.x, v0.y, v0.z, v0.w, v1.x, v1.y, v1.z, v1.w};
        #pragma unroll
        for (int j = 0; j < 8; j++) {
            __nv_bfloat16 hb = __float2bfloat16(vv[j]);
            __nv_bfloat16 lb = __float2bfloat16(vv[j] - __bfloat162float(hb));
            Ah[r * 16 + half + j] = __bfloat16_as_ushort(hb);
            Al[r * 16 + half + j] = __bfloat16_as_ushort(lb);
        }
    }
    {
        int k = tid >> 4, n0 = (tid & 15) * 8;
        #pragma unroll
        for (int j = 0; j < 8; j++) {
            float v = we[k * HC + n0 + j];
            __nv_bfloat16 hb = __float2bfloat16(v);
            __nv_bfloat16 lb = __float2bfloat16(v - __bfloat162float(hb));
            Bh[(n0 + j) * 16 + k] = __bfloat16_as_ushort(hb);
            Bl[(n0 + j) * 16 + k] = __bfloat16_as_ushort(lb);
        }
    }
    __syncthreads();

    int w = tid >> 5, lane = tid & 31;
    int g = lane >> 2, t = lane & 3;
    int mw = w >> 1, nw = w & 1;

    float acc[2][8][4];
    #pragma unroll
    for (int a = 0; a < 2; a++)
        #pragma unroll
        for (int b = 0; b < 8; b++)
            #pragma unroll
            for (int c = 0; c < 4; c++) acc[a][b][c] = 0.f;

    #pragma unroll
    for (int s = 0; s < 3; s++) {
        const unsigned short* A = (s == 2) ? Al : Ah;
        const unsigned short* B = (s == 1) ? Bl : Bh;
        uint32_t bf[8][2];
        #pragma unroll
        for (int nt = 0; nt < 8; nt++) {
            const unsigned short* p = &B[(nw * 64 + nt * 8 + g) * 16 + t * 2];
            bf[nt][0] = *(const uint32_t*)p;
            bf[nt][1] = *(const uint32_t*)(p + 8);
        }
        #pragma unroll
        for (int mt = 0; mt < 2; mt++) {
            const unsigned short* p = &A[(mw * 32 + mt * 16 + g) * 16 + t * 2];
            uint32_t a0 = *(const uint32_t*)p;
            uint32_t a1 = *(const uint32_t*)(p + 8 * 16);
            uint32_t a2 = *(const uint32_t*)(p + 8);
            uint32_t a3 = *(const uint32_t*)(p + 8 * 16 + 8);
            #pragma unroll
            for (int nt = 0; nt < 8; nt++) {
                asm volatile(
                    "mma.sync.aligned.m16n8k16.row.col.f32.bf16.bf16.f32 "
                    "{%0,%1,%2,%3}, {%4,%5,%6,%7}, {%8,%9}, {%0,%1,%2,%3};"
                    : "+f"(acc[mt][nt][0]), "+f"(acc[mt][nt][1]),
                      "+f"(acc[mt][nt][2]), "+f"(acc[mt][nt][3])
                    : "r"(a0), "r"(a1), "r"(a2), "r"(a3),
                      "r"(bf[nt][0]), "r"(bf[nt][1]));
            }
        }
    }

    #pragma unroll
    for (int mt = 0; mt < 2; mt++) {
        int r0 = e0 + mw * 32 + mt * 16 + g;
        int r1 = r0 + 8;
        #pragma unroll
        for (int nt = 0; nt < 8; nt++) {
            int col = nw * 64 + nt * 8 + t * 2;
            if (r0 < EE) {
                __half2 h0 = __floats2half2_rn(acc[mt][nt][0], acc[mt][nt][1]);
                *(__half2*)&g_e[(size_t)r0 * HC + col] = h0;
            }
            if (r1 < EE) {
                __half2 h1 = __floats2half2_rn(acc[mt][nt][2], acc[mt][nt][3]);
                *(__half2*)&g_e[(size_t)r1 * HC + col] = h1;
            }
        }
    }
}

// ---------------------------------------------------------------------------
// Sorted-scatter edge kernel (R9 version — prefetch reverted)
// ---------------------------------------------------------------------------
__global__ __launch_bounds__(256) void edge_sorted_kernel()
{
    int lane = threadIdx.x & 31;
    int w = (blockIdx.x * 256 + threadIdx.x) >> 5;
    int base = w * CHUNK;
    if (base >= EE) return;
    int end = (base + CHUNK < EE) ? base + CHUNK : EE;

    int c0 = lane << 2;
    int head = lane >> 2;

    int cur_dst = -1;
    float4 q4 = make_float4(0.f, 0.f, 0.f, 0.f);
    float nx = 0.f, ny = 0.f, nz = 0.f, nw4 = 0.f, den = 0.f;

    for (int i = base; i < end; i++) {
        int4 sde = g_sde[i];
        int src = sde.x, dst = sde.y, eid = sde.z;

        if (dst != cur_dst) {
            if (cur_dst >= 0) {
                float* op = g_attn + (size_t)cur_dst * HC + c0;
                asm volatile("red.global.add.v4.f32 [%0], {%1, %2, %3, %4};"
                             :: "l"(op), "f"(nx), "f"(ny), "f"(nz), "f"(nw4)
                             : "memory");
                if ((lane & 3) == 0) {
                    float* dp = &g_sum[cur_dst * HH + head];
                    asm volatile("red.global.add.f32 [%0], %1;"
                                 :: "l"(dp), "f"(den) : "memory");
                }
            }
            cur_dst = dst;
            q4 = *(const float4*)&g_q[dst * HC + c0];
            nx = ny = nz = nw4 = den = 0.f;
        }

        uint2 eu = *(const uint2*)&g_e[(size_t)eid * HC + c0];
        float2 f01 = __half22float2(*reinterpret_cast<__half2*>(&eu.x));
        float2 f23 = __half22float2(*reinterpret_cast<__half2*>(&eu.y));
        float ex = f01.x, ey = f01.y, ez = f23.x, ew = f23.y;

        float4 k4 = *(const float4*)&g_k[src * HC + c0];
        float s = q4.x * (k4.x + ex) + q4.y * (k4.y + ey)
                + q4.z * (k4.z + ez) + q4.w * (k4.w + ew);
        s += __shfl_xor_sync(0xffffffffu, s, 1);
        s += __shfl_xor_sync(0xffffffffu, s, 2);

        float p = __expf(s * 0.25f);

        float4 v4 = *(const float4*)&g_v[src * HC + c0];
        nx  += (v4.x + ex) * p;
        ny  += (v4.y + ey) * p;
        nz  += (v4.z + ez) * p;
        nw4 += (v4.w + ew) * p;
        den += p;
    }

    if (cur_dst >= 0) {
        float* op = g_attn + (size_t)cur_dst * HC + c0;
        asm volatile("red.global.add.v4.f32 [%0], {%1, %2, %3, %4};"
                     :: "l"(op), "f"(nx), "f"(ny), "f"(nz), "f"(nw4)
                     : "memory");
        if ((lane & 3) == 0) {
            float* dp = &g_sum[cur_dst * HH + head];
            asm volatile("red.global.add.f32 [%0], %1;"
                         :: "l"(dp), "f"(den) : "memory");
        }
    }
}

// ---------------------------------------------------------------------------
__global__ __launch_bounds__(256) void normalize_kernel(float* __restrict__ out)
{
    int i = blockIdx.x * blockDim.x + threadIdx.x;
    int n4 = (NN * HC) / 4;
    if (i >= n4) return;
    int node = i >> 5;
    int head = (i & 31) >> 2;
    float inv = 1.f / (g_sum[node * HH + head] + 1e-16f);
    float4 a = ((const float4*)g_attn)[i];
    float4 o = ((float4*)out)[i];
    o.x += a.x * inv; o.y += a.y * inv;
    o.z += a.z * inv; o.w += a.w * inv;
    ((float4*)out)[i] = o;
}

// ---------------------------------------------------------------------------
extern "C" void kernel_launch(void* const* d_in, const int* in_sizes, int n_in,
                              void* d_out, int out_size)
{
    const float* x  = (const float*)d_in[0];
    const int*   ei = (const int*)d_in[1];
    const float* ea = (const float*)d_in[2];
    const float* wq = (const float*)d_in[3];
    const float* bq = (const float*)d_in[4];
    const float* wk = (const float*)d_in[5];
    const float* bk = (const float*)d_in[6];
    const float* wv = (const float*)d_in[7];
    const float* bv = (const float*)d_in[8];
    const float* we = (const float*)d_in[9];
    const float* ws = (const float*)d_in[10];
    const float* bs = (const float*)d_in[11];
    float* out = (float*)d_out;

    static bool attr_set = false;
    if (!attr_set) {
        cudaFuncSetAttribute(mma_gemm_kernel,
                             cudaFuncAttributeMaxDynamicSharedMemorySize, SM_TOT);
        attr_set = true;
    }

    // 4th launch = ncu's captured slot -> mma_gemm (verify ldmatrix win)
    zero_kernel<<<((NN * HC) / 4 + 255) / 256, 256>>>();
    convert_x_kernel<<<((NN * INF) / 4 + 255) / 256, 256>>>(x);
    dim3 gw(64, 4);
    convert_w_kernel<<<gw, 256>>>(wq, wk, wv, ws);
    mma_gemm_kernel<<<391, 256, SM_TOT>>>(bq, bk, bv, bs, out);   // 4th: profiled

    hist_kernel<<<(EE + 255) / 256, 256>>>(ei);
    scan1_kernel<<<196, 256>>>();
    scan2_kernel<<<1, 256>>>();
    scan3_kernel<<<NPAD / 256, 256>>>();
    permute_kernel<<<(EE + 255) / 256, 256>>>(ei);

    egemm_kernel<<<(EE + EG_ROWS - 1) / EG_ROWS, 256>>>(ea, we);

    int warps = (EE + CHUNK - 1) / CHUNK;
    edge_sorted_kernel<<<(warps * 32 + 255) / 256, 256>>>();

    normalize_kernel<<<((NN * HC) / 4 + 255) / 256, 256>>>(out);
}

// round 12
// speedup vs baseline: 1.2102x; 1.0422x over previous
#include <cuda_runtime.h>
#include <cuda_bf16.h>
#include <cuda_fp16.h>
#include <cstdint>

#define NN 50000
#define EE 800000
#define INF 128
#define HC 128
#define HH 8
#define ED 16

#define NPAD 50176            // 196 * 256, >= NN+1
#define CHUNK 16              // sorted edges per warp
#define EG_ROWS 128           // edges per egemm CTA

// ---- scratch (device globals; no allocation allowed) ----
__device__ __align__(16) float g_q[NN * HC];
__device__ __align__(16) __half g_kh[NN * HC];    // k in fp16 (gather traffic /2)
__device__ __align__(16) __half g_vh[NN * HC];    // v in fp16
__device__ __align__(16) float g_attn[NN * HC];   // unnormalized numerator
__device__ __align__(16) float g_sum[NN * HH];    // softmax denominator
__device__ int g_cnt[NPAD];        // per-dst degree histogram (zero-padded)
__device__ int g_rowptr[NPAD];     // exclusive prefix sum
__device__ int g_wcnt[NN];         // write cursors for permute
__device__ int g_blk[256];         // per-block sums for scan
__device__ __align__(16) int4 g_sde[EE];  // (src, dst, eid) sorted by dst

// bf16 hi/lo scratch
__device__ __align__(16) unsigned short g_xh[NPAD * INF];
__device__ __align__(16) unsigned short g_xl[NPAD * INF];
__device__ __align__(16) unsigned short g_wh[4][HC * INF];  // [n][k] layout
__device__ __align__(16) unsigned short g_wl[4][HC * INF];

// precomputed edge bias  e = edge_attr @ w_e, fp16 [E][128]
__device__ __align__(16) __half g_e[(size_t)EE * HC];

// ---------------------------------------------------------------------------
__global__ void zero_kernel() {
    int i = blockIdx.x * blockDim.x + threadIdx.x;
    if (i < NPAD) g_cnt[i] = 0;
    int n4 = (NN * HC) / 4;
    if (i < n4) ((float4*)g_attn)[i] = make_float4(0.f, 0.f, 0.f, 0.f);
    if (i < NN * HH) g_sum[i] = 0.f;
}

__global__ void hist_kernel(const int* __restrict__ ei) {
    int e = blockIdx.x * blockDim.x + threadIdx.x;
    if (e < EE) atomicAdd(&g_cnt[ei[EE + e]], 1);
}

__global__ void scan1_kernel() {
    __shared__ int s[256];
    int t = threadIdx.x;
    int i = blockIdx.x * 256 + t;
    int v = g_cnt[i];
    s[t] = v;
    __syncthreads();
    #pragma unroll
    for (int off = 1; off < 256; off <<= 1) {
        int u = (t >= off) ? s[t - off] : 0;
        __syncthreads();
        s[t] += u;
        __syncthreads();
    }
    g_rowptr[i] = s[t] - v;
    if (t == 255) g_blk[blockIdx.x] = s[255];
}

__global__ void scan2_kernel() {
    __shared__ int s[256];
    int t = threadIdx.x;
    int v = (t < 196) ? g_blk[t] : 0;
    s[t] = v;
    __syncthreads();
    #pragma unroll
    for (int off = 1; off < 256; off <<= 1) {
        int u = (t >= off) ? s[t - off] : 0;
        __syncthreads();
        s[t] += u;
        __syncthreads();
    }
    if (t < 196) g_blk[t] = s[t] - v;
}

__global__ void scan3_kernel() {
    int i = blockIdx.x * blockDim.x + threadIdx.x;
    if (i < NPAD) {
        int v = g_rowptr[i] + g_blk[i >> 8];
        g_rowptr[i] = v;
        if (i < NN) g_wcnt[i] = v;
    }
}

__global__ void permute_kernel(const int* __restrict__ ei) {
    int e = blockIdx.x * blockDim.x + threadIdx.x;
    if (e < EE) {
        int src = ei[e];
        int dst = ei[EE + e];
        int pos = atomicAdd(&g_wcnt[dst], 1);
        g_sde[pos] = make_int4(src, dst, e, 0);
    }
}

// ---------------------------------------------------------------------------
// convert x (fp32 [m][k]) -> bf16 hi/lo, same layout
// ---------------------------------------------------------------------------
__global__ void convert_x_kernel(const float* __restrict__ x) {
    int i = blockIdx.x * blockDim.x + threadIdx.x;   // float4 index
    if (i >= (NN * INF) / 4) return;
    float4 v = ((const float4*)x)[i];
    float vv[4] = {v.x, v.y, v.z, v.w};
    unsigned short h[4], l[4];
    #pragma unroll
    for (int j = 0; j < 4; j++) {
        __nv_bfloat16 hb = __float2bfloat16(vv[j]);
        __nv_bfloat16 lb = __float2bfloat16(vv[j] - __bfloat162float(hb));
        h[j] = __bfloat16_as_ushort(hb);
        l[j] = __bfloat16_as_ushort(lb);
    }
    uint2 ph = make_uint2((uint32_t)h[0] | ((uint32_t)h[1] << 16),
                          (uint32_t)h[2] | ((uint32_t)h[3] << 16));
    uint2 pl = make_uint2((uint32_t)l[0] | ((uint32_t)l[1] << 16),
                          (uint32_t)l[2] | ((uint32_t)l[3] << 16));
    ((uint2*)g_xh)[i] = ph;
    ((uint2*)g_xl)[i] = pl;
}

// ---------------------------------------------------------------------------
// convert W (fp32 [k][n]) -> bf16 hi/lo, TRANSPOSED to [n][k]
// ---------------------------------------------------------------------------
__global__ void convert_w_kernel(
    const float* __restrict__ wq, const float* __restrict__ wk,
    const float* __restrict__ wv, const float* __restrict__ ws)
{
    int m = blockIdx.y;
    const float* W = (m == 0) ? wq : (m == 1) ? wk : (m == 2) ? wv : ws;
    int idx = blockIdx.x * 256 + threadIdx.x;  // 0..16383
    int n = idx & 127, k = idx >> 7;
    float v = W[k * HC + n];
    __nv_bfloat16 hb = __float2bfloat16(v);
    __nv_bfloat16 lb = __float2bfloat16(v - __bfloat162float(hb));
    g_wh[m][n * INF + k] = __bfloat16_as_ushort(hb);
    g_wl[m][n * INF + k] = __bfloat16_as_ushort(lb);
}

// ---------------------------------------------------------------------------
// HMMA GEMM: D = x@W + b for 4 matrices, bf16 hi/lo split (3 terms).
// CTA = 128x128 tile, 8 warps (2x4), warp tile 64x32, m16n8k16 atoms.
// Scalar-LDS fragment loads (R9-proven; ldmatrix variant regressed).
// k and v results stored as fp16 for the edge-gather phase.
// ---------------------------------------------------------------------------
#define ASTRIDE 272          // bytes per smem row (136 bf16)
#define SM_A_H  0            // 128*272 = 34816
#define SM_A_L  34816
#define SM_B_H  69632
#define SM_B_L  104448
#define SM_BIAS 139264       // 512 floats = 2048
#define SM_TOT  141312

__global__ __launch_bounds__(256, 1) void mma_gemm_kernel(
    const float* __restrict__ bq, const float* __restrict__ bk,
    const float* __restrict__ bv, const float* __restrict__ bs,
    float* __restrict__ out)
{
    extern __shared__ char sm[];
    int tid = threadIdx.x;
    int w = tid >> 5;
    int lane = tid & 31;
    int g = lane >> 2;        // 0..7
    int t = lane & 3;         // 0..3
    int mw = w >> 2;          // 0..1
    int nw = w & 3;           // 0..3
    int rowBase = blockIdx.x * 128;

    #pragma unroll
    for (int i = 0; i < 8; i++) {
        int idx = tid + i * 256;          // 0..2047
        int r = idx >> 4;                 // row 0..127
        int kc = idx & 15;                // 8-bf16 chunk
        size_t src = ((size_t)(rowBase + r) * INF + kc * 8) * 2;
        *(uint4*)(sm + SM_A_H + r * ASTRIDE + kc * 16) =
            *(const uint4*)((const char*)g_xh + src);
        *(uint4*)(sm + SM_A_L + r * ASTRIDE + kc * 16) =
            *(const uint4*)((const char*)g_xl + src);
    }
    for (int j = tid; j < 512; j += 256) {
        int m = j >> 7, c = j & 127;
        const float* B = (m == 0) ? bq : (m == 1) ? bk : (m == 2) ? bv : bs;
        *(float*)(sm + SM_BIAS + j * 4) = B[c];
    }

    for (int m = 0; m < 4; m++) {
        __syncthreads();     // protect previous B from overwrite
        #pragma unroll
        for (int i = 0; i < 8; i++) {
            int idx = tid + i * 256;
            int n = idx >> 4;
            int kc = idx & 15;
            size_t src = ((size_t)n * INF + kc * 8) * 2;
            *(uint4*)(sm + SM_B_H + n * ASTRIDE + kc * 16) =
                *(const uint4*)((const char*)g_wh[m] + src);
            *(uint4*)(sm + SM_B_L + n * ASTRIDE + kc * 16) =
                *(const uint4*)((const char*)g_wl[m] + src);
        }
        __syncthreads();

        float acc[4][4][4];
        #pragma unroll
        for (int a = 0; a < 4; a++)
            #pragma unroll
            for (int b = 0; b < 4; b++)
                #pragma unroll
                for (int c = 0; c < 4; c++) acc[a][b][c] = 0.f;

        #pragma unroll
        for (int s = 0; s < 3; s++) {
            const char* Ab = sm + ((s == 2) ? SM_A_L : SM_A_H);
            const char* Bb = sm + ((s == 1) ? SM_B_L : SM_B_H);
            #pragma unroll
            for (int kt = 0; kt < 8; kt++) {
                int kb = (kt * 16 + t * 2) * 2;
                uint32_t bf[4][2];
                #pragma unroll
                for (int nt = 0; nt < 4; nt++) {
                    const char* p = Bb + (nw * 32 + nt * 8 + g) * ASTRIDE + kb;
                    bf[nt][0] = *(const uint32_t*)p;
                    bf[nt][1] = *(const uint32_t*)(p + 16);
                }
                #pragma unroll
                for (int mt = 0; mt < 4; mt++) {
                    const char* p = Ab + (mw * 64 + mt * 16 + g) * ASTRIDE + kb;
                    uint32_t a0 = *(const uint32_t*)p;
                    uint32_t a1 = *(const uint32_t*)(p + 8 * ASTRIDE);
                    uint32_t a2 = *(const uint32_t*)(p + 16);
                    uint32_t a3 = *(const uint32_t*)(p + 8 * ASTRIDE + 16);
                    #pragma unroll
                    for (int nt = 0; nt < 4; nt++) {
                        asm volatile(
                            "mma.sync.aligned.m16n8k16.row.col.f32.bf16.bf16.f32 "
                            "{%0,%1,%2,%3}, {%4,%5,%6,%7}, {%8,%9}, {%0,%1,%2,%3};"
                            : "+f"(acc[mt][nt][0]), "+f"(acc[mt][nt][1]),
                              "+f"(acc[mt][nt][2]), "+f"(acc[mt][nt][3])
                            : "r"(a0), "r"(a1), "r"(a2), "r"(a3),
                              "r"(bf[nt][0]), "r"(bf[nt][1]));
                    }
                }
            }
        }

        const float* sb = (const float*)(sm + SM_BIAS) + m * 128;
        if (m == 1 || m == 2) {
            // k, v -> fp16
            __half* O = (m == 1) ? g_kh : g_vh;
            #pragma unroll
            for (int mt = 0; mt < 4; mt++) {
                int r0 = rowBase + mw * 64 + mt * 16 + g;
                int r1 = r0 + 8;
                #pragma unroll
                for (int nt = 0; nt < 4; nt++) {
                    int col = nw * 32 + nt * 8 + t * 2;
                    float bx = sb[col], by = sb[col + 1];
                    if (r0 < NN)
                        *(__half2*)&O[(size_t)r0 * HC + col] =
                            __floats2half2_rn(acc[mt][nt][0] + bx,
                                              acc[mt][nt][1] + by);
                    if (r1 < NN)
                        *(__half2*)&O[(size_t)r1 * HC + col] =
                            __floats2half2_rn(acc[mt][nt][2] + bx,
                                              acc[mt][nt][3] + by);
                }
            }
        } else {
            float* O = (m == 0) ? g_q : out;
            #pragma unroll
            for (int mt = 0; mt < 4; mt++) {
                int r0 = rowBase + mw * 64 + mt * 16 + g;
                int r1 = r0 + 8;
                #pragma unroll
                for (int nt = 0; nt < 4; nt++) {
                    int col = nw * 32 + nt * 8 + t * 2;
                    float bx = sb[col], by = sb[col + 1];
                    if (r0 < NN) {
                        float2 o0 = make_float2(acc[mt][nt][0] + bx,
                                                acc[mt][nt][1] + by);
                        *(float2*)&O[(size_t)r0 * HC + col] = o0;
                    }
                    if (r1 < NN) {
                        float2 o1 = make_float2(acc[mt][nt][2] + bx,
                                                acc[mt][nt][3] + by);
                        *(float2*)&O[(size_t)r1 * HC + col] = o1;
                    }
                }
            }
        }
    }
}

// ---------------------------------------------------------------------------
// egemm: E = edge_attr @ w_e -> g_e (fp16 [E][128]).
// ---------------------------------------------------------------------------
__global__ __launch_bounds__(256) void egemm_kernel(
    const float* __restrict__ ea, const float* __restrict__ we)
{
    __shared__ unsigned short Ah[EG_ROWS * 16], Al[EG_ROWS * 16];
    __shared__ unsigned short Bh[HC * 16], Bl[HC * 16];

    int tid = threadIdx.x;
    int e0 = blockIdx.x * EG_ROWS;

    {
        int r = tid >> 1, half = (tid & 1) * 8;
        int ge = e0 + r;
        float4 v0, v1;
        if (ge < EE) {
            v0 = *(const float4*)&ea[(size_t)ge * ED + half];
            v1 = *(const float4*)&ea[(size_t)ge * ED + half + 4];
        } else {
            v0 = v1 = make_float4(0.f, 0.f, 0.f, 0.f);
        }
        float vv[8] = {v0.x, v0.y, v0.z, v0.w, v1.x, v1.y, v1.z, v1.w};
        #pragma unroll
        for (int j = 0; j < 8; j++) {
            __nv_bfloat16 hb = __float2bfloat16(vv[j]);
            __nv_bfloat16 lb = __float2bfloat16(vv[j] - __bfloat162float(hb));
            Ah[r * 16 + half + j] = __bfloat16_as_ushort(hb);
            Al[r * 16 + half + j] = __bfloat16_as_ushort(lb);
        }
    }
    {
        int k = tid >> 4, n0 = (tid & 15) * 8;
        #pragma unroll
        for (int j = 0; j < 8; j++) {
            float v = we[k * HC + n0 + j];
            __nv_bfloat16 hb = __float2bfloat16(v);
            __nv_bfloat16 lb = __float2bfloat16(v - __bfloat162float(hb));
            Bh[(n0 + j) * 16 + k] = __bfloat16_as_ushort(hb);
            Bl[(n0 + j) * 16 + k] = __bfloat16_as_ushort(lb);
        }
    }
    __syncthreads();

    int w = tid >> 5, lane = tid & 31;
    int g = lane >> 2, t = lane & 3;
    int mw = w >> 1, nw = w & 1;

    float acc[2][8][4];
    #pragma unroll
    for (int a = 0; a < 2; a++)
        #pragma unroll
        for (int b = 0; b < 8; b++)
            #pragma unroll
            for (int c = 0; c < 4; c++) acc[a][b][c] = 0.f;

    #pragma unroll
    for (int s = 0; s < 3; s++) {
        const unsigned short* A = (s == 2) ? Al : Ah;
        const unsigned short* B = (s == 1) ? Bl : Bh;
        uint32_t bf[8][2];
        #pragma unroll
        for (int nt = 0; nt < 8; nt++) {
            const unsigned short* p = &B[(nw * 64 + nt * 8 + g) * 16 + t * 2];
            bf[nt][0] = *(const uint32_t*)p;
            bf[nt][1] = *(const uint32_t*)(p + 8);
        }
        #pragma unroll
        for (int mt = 0; mt < 2; mt++) {
            const unsigned short* p = &A[(mw * 32 + mt * 16 + g) * 16 + t * 2];
            uint32_t a0 = *(const uint32_t*)p;
            uint32_t a1 = *(const uint32_t*)(p + 8 * 16);
            uint32_t a2 = *(const uint32_t*)(p + 8);
            uint32_t a3 = *(const uint32_t*)(p + 8 * 16 + 8);
            #pragma unroll
            for (int nt = 0; nt < 8; nt++) {
                asm volatile(
                    "mma.sync.aligned.m16n8k16.row.col.f32.bf16.bf16.f32 "
                    "{%0,%1,%2,%3}, {%4,%5,%6,%7}, {%8,%9}, {%0,%1,%2,%3};"
                    : "+f"(acc[mt][nt][0]), "+f"(acc[mt][nt][1]),
                      "+f"(acc[mt][nt][2]), "+f"(acc[mt][nt][3])
                    : "r"(a0), "r"(a1), "r"(a2), "r"(a3),
                      "r"(bf[nt][0]), "r"(bf[nt][1]));
            }
        }
    }

    #pragma unroll
    for (int mt = 0; mt < 2; mt++) {
        int r0 = e0 + mw * 32 + mt * 16 + g;
        int r1 = r0 + 8;
        #pragma unroll
        for (int nt = 0; nt < 8; nt++) {
            int col = nw * 64 + nt * 8 + t * 2;
            if (r0 < EE) {
                __half2 h0 = __floats2half2_rn(acc[mt][nt][0], acc[mt][nt][1]);
                *(__half2*)&g_e[(size_t)r0 * HC + col] = h0;
            }
            if (r1 < EE) {
                __half2 h1 = __floats2half2_rn(acc[mt][nt][2], acc[mt][nt][3]);
                *(__half2*)&g_e[(size_t)r1 * HC + col] = h1;
            }
        }
    }
}

// ---------------------------------------------------------------------------
// Sorted-scatter edge kernel: k/v/e all fp16 gathers (8B per lane each).
// ---------------------------------------------------------------------------
__global__ __launch_bounds__(256) void edge_sorted_kernel()
{
    int lane = threadIdx.x & 31;
    int w = (blockIdx.x * 256 + threadIdx.x) >> 5;
    int base = w * CHUNK;
    if (base >= EE) return;
    int end = (base + CHUNK < EE) ? base + CHUNK : EE;

    int c0 = lane << 2;
    int head = lane >> 2;

    int cur_dst = -1;
    float4 q4 = make_float4(0.f, 0.f, 0.f, 0.f);
    float nx = 0.f, ny = 0.f, nz = 0.f, nw4 = 0.f, den = 0.f;

    for (int i = base; i < end; i++) {
        int4 sde = g_sde[i];
        int src = sde.x, dst = sde.y, eid = sde.z;

        if (dst != cur_dst) {
            if (cur_dst >= 0) {
                float* op = g_attn + (size_t)cur_dst * HC + c0;
                asm volatile("red.global.add.v4.f32 [%0], {%1, %2, %3, %4};"
                             :: "l"(op), "f"(nx), "f"(ny), "f"(nz), "f"(nw4)
                             : "memory");
                if ((lane & 3) == 0) {
                    float* dp = &g_sum[cur_dst * HH + head];
                    asm volatile("red.global.add.f32 [%0], %1;"
                                 :: "l"(dp), "f"(den) : "memory");
                }
            }
            cur_dst = dst;
            q4 = *(const float4*)&g_q[dst * HC + c0];
            nx = ny = nz = nw4 = den = 0.f;
        }

        uint2 eu = *(const uint2*)&g_e[(size_t)eid * HC + c0];
        float2 e01 = __half22float2(*reinterpret_cast<__half2*>(&eu.x));
        float2 e23 = __half22float2(*reinterpret_cast<__half2*>(&eu.y));

        uint2 ku = *(const uint2*)&g_kh[(size_t)src * HC + c0];
        float2 k01 = __half22float2(*reinterpret_cast<__half2*>(&ku.x));
        float2 k23 = __half22float2(*reinterpret_cast<__half2*>(&ku.y));

        float s = q4.x * (k01.x + e01.x) + q4.y * (k01.y + e01.y)
                + q4.z * (k23.x + e23.x) + q4.w * (k23.y + e23.y);
        s += __shfl_xor_sync(0xffffffffu, s, 1);
        s += __shfl_xor_sync(0xffffffffu, s, 2);

        float p = __expf(s * 0.25f);

        uint2 vu = *(const uint2*)&g_vh[(size_t)src * HC + c0];
        float2 v01 = __half22float2(*reinterpret_cast<__half2*>(&vu.x));
        float2 v23 = __half22float2(*reinterpret_cast<__half2*>(&vu.y));

        nx  += (v01.x + e01.x) * p;
        ny  += (v01.y + e01.y) * p;
        nz  += (v23.x + e23.x) * p;
        nw4 += (v23.y + e23.y) * p;
        den += p;
    }

    if (cur_dst >= 0) {
        float* op = g_attn + (size_t)cur_dst * HC + c0;
        asm volatile("red.global.add.v4.f32 [%0], {%1, %2, %3, %4};"
                     :: "l"(op), "f"(nx), "f"(ny), "f"(nz), "f"(nw4)
                     : "memory");
        if ((lane & 3) == 0) {
            float* dp = &g_sum[cur_dst * HH + head];
            asm volatile("red.global.add.f32 [%0], %1;"
                         :: "l"(dp), "f"(den) : "memory");
        }
    }
}

// ---------------------------------------------------------------------------
__global__ __launch_bounds__(256) void normalize_kernel(float* __restrict__ out)
{
    int i = blockIdx.x * blockDim.x + threadIdx.x;
    int n4 = (NN * HC) / 4;
    if (i >= n4) return;
    int node = i >> 5;
    int head = (i & 31) >> 2;
    float inv = 1.f / (g_sum[node * HH + head] + 1e-16f);
    float4 a = ((const float4*)g_attn)[i];
    float4 o = ((float4*)out)[i];
    o.x += a.x * inv; o.y += a.y * inv;
    o.z += a.z * inv; o.w += a.w * inv;
    ((float4*)out)[i] = o;
}

// ---------------------------------------------------------------------------
extern "C" void kernel_launch(void* const* d_in, const int* in_sizes, int n_in,
                              void* d_out, int out_size)
{
    const float* x  = (const float*)d_in[0];
    const int*   ei = (const int*)d_in[1];
    const float* ea = (const float*)d_in[2];
    const float* wq = (const float*)d_in[3];
    const float* bq = (const float*)d_in[4];
    const float* wk = (const float*)d_in[5];
    const float* bk = (const float*)d_in[6];
    const float* wv = (const float*)d_in[7];
    const float* bv = (const float*)d_in[8];
    const float* we = (const float*)d_in[9];
    const float* ws = (const float*)d_in[10];
    const float* bs = (const float*)d_in[11];
    float* out = (float*)d_out;

    static bool attr_set = false;
    if (!attr_set) {
        cudaFuncSetAttribute(mma_gemm_kernel,
                             cudaFuncAttributeMaxDynamicSharedMemorySize, SM_TOT);
        attr_set = true;
    }

    // 4th launch = ncu's captured slot -> mma_gemm
    zero_kernel<<<((NN * HC) / 4 + 255) / 256, 256>>>();
    convert_x_kernel<<<((NN * INF) / 4 + 255) / 256, 256>>>(x);
    dim3 gw(64, 4);
    convert_w_kernel<<<gw, 256>>>(wq, wk, wv, ws);
    mma_gemm_kernel<<<391, 256, SM_TOT>>>(bq, bk, bv, bs, out);   // 4th: profiled

    hist_kernel<<<(EE + 255) / 256, 256>>>(ei);
    scan1_kernel<<<196, 256>>>();
    scan2_kernel<<<1, 256>>>();
    scan3_kernel<<<NPAD / 256, 256>>>();
    permute_kernel<<<(EE + 255) / 256, 256>>>(ei);

    egemm_kernel<<<(EE + EG_ROWS - 1) / EG_ROWS, 256>>>(ea, we);

    int warps = (EE + CHUNK - 1) / CHUNK;
    edge_sorted_kernel<<<(warps * 32 + 255) / 256, 256>>>();

    normalize_kernel<<<((NN * HC) / 4 + 255) / 256, 256>>>(out);
}

// round 13
// speedup vs baseline: 1.4280x; 1.1800x over previous
#include <cuda_runtime.h>
#include <cuda_bf16.h>
#include <cuda_fp16.h>
#include <cstdint>

#define NN 50000
#define EE 800000
#define INF 128
#define HC 128
#define HH 8
#define ED 16

#define NPAD 50176            // 196 * 256, >= NN+1
#define FE_ROWS 128           // sorted edges per fused CTA (EE % 128 == 0)

// ---- scratch (device globals; no allocation allowed) ----
__device__ __align__(16) float g_q[NN * HC];
__device__ __align__(16) __half g_kh[NN * HC];    // k in fp16
__device__ __align__(16) __half g_vh[NN * HC];    // v in fp16
__device__ __align__(16) float g_attn[NN * HC];   // unnormalized numerator
__device__ __align__(16) float g_sum[NN * HH];    // softmax denominator
__device__ int g_cnt[NPAD];        // per-dst degree histogram (zero-padded)
__device__ int g_rowptr[NPAD];     // exclusive prefix sum
__device__ int g_wcnt[NN];         // write cursors for permute
__device__ int g_blk[256];         // per-block sums for scan
__device__ __align__(16) int4 g_sde[EE];  // (src, dst, eid) sorted by dst

// bf16 hi/lo scratch
__device__ __align__(16) unsigned short g_xh[NPAD * INF];
__device__ __align__(16) unsigned short g_xl[NPAD * INF];
__device__ __align__(16) unsigned short g_wh[4][HC * INF];  // [n][k] layout
__device__ __align__(16) unsigned short g_wl[4][HC * INF];

// ---------------------------------------------------------------------------
__global__ void zero_kernel() {
    int i = blockIdx.x * blockDim.x + threadIdx.x;
    if (i < NPAD) g_cnt[i] = 0;
    int n4 = (NN * HC) / 4;
    if (i < n4) ((float4*)g_attn)[i] = make_float4(0.f, 0.f, 0.f, 0.f);
    if (i < NN * HH) g_sum[i] = 0.f;
}

__global__ void hist_kernel(const int* __restrict__ ei) {
    int e = blockIdx.x * blockDim.x + threadIdx.x;
    if (e < EE) atomicAdd(&g_cnt[ei[EE + e]], 1);
}

__global__ void scan1_kernel() {
    __shared__ int s[256];
    int t = threadIdx.x;
    int i = blockIdx.x * 256 + t;
    int v = g_cnt[i];
    s[t] = v;
    __syncthreads();
    #pragma unroll
    for (int off = 1; off < 256; off <<= 1) {
        int u = (t >= off) ? s[t - off] : 0;
        __syncthreads();
        s[t] += u;
        __syncthreads();
    }
    g_rowptr[i] = s[t] - v;
    if (t == 255) g_blk[blockIdx.x] = s[255];
}

__global__ void scan2_kernel() {
    __shared__ int s[256];
    int t = threadIdx.x;
    int v = (t < 196) ? g_blk[t] : 0;
    s[t] = v;
    __syncthreads();
    #pragma unroll
    for (int off = 1; off < 256; off <<= 1) {
        int u = (t >= off) ? s[t - off] : 0;
        __syncthreads();
        s[t] += u;
        __syncthreads();
    }
    if (t < 196) g_blk[t] = s[t] - v;
}

__global__ void scan3_kernel() {
    int i = blockIdx.x * blockDim.x + threadIdx.x;
    if (i < NPAD) {
        int v = g_rowptr[i] + g_blk[i >> 8];
        g_rowptr[i] = v;
        if (i < NN) g_wcnt[i] = v;
    }
}

__global__ void permute_kernel(const int* __restrict__ ei) {
    int e = blockIdx.x * blockDim.x + threadIdx.x;
    if (e < EE) {
        int src = ei[e];
        int dst = ei[EE + e];
        int pos = atomicAdd(&g_wcnt[dst], 1);
        g_sde[pos] = make_int4(src, dst, e, 0);
    }
}

// ---------------------------------------------------------------------------
// convert x (fp32 [m][k]) -> bf16 hi/lo, same layout
// ---------------------------------------------------------------------------
__global__ void convert_x_kernel(const float* __restrict__ x) {
    int i = blockIdx.x * blockDim.x + threadIdx.x;   // float4 index
    if (i >= (NN * INF) / 4) return;
    float4 v = ((const float4*)x)[i];
    float vv[4] = {v.x, v.y, v.z, v.w};
    unsigned short h[4], l[4];
    #pragma unroll
    for (int j = 0; j < 4; j++) {
        __nv_bfloat16 hb = __float2bfloat16(vv[j]);
        __nv_bfloat16 lb = __float2bfloat16(vv[j] - __bfloat162float(hb));
        h[j] = __bfloat16_as_ushort(hb);
        l[j] = __bfloat16_as_ushort(lb);
    }
    uint2 ph = make_uint2((uint32_t)h[0] | ((uint32_t)h[1] << 16),
                          (uint32_t)h[2] | ((uint32_t)h[3] << 16));
    uint2 pl = make_uint2((uint32_t)l[0] | ((uint32_t)l[1] << 16),
                          (uint32_t)l[2] | ((uint32_t)l[3] << 16));
    ((uint2*)g_xh)[i] = ph;
    ((uint2*)g_xl)[i] = pl;
}

// ---------------------------------------------------------------------------
// convert W (fp32 [k][n]) -> bf16 hi/lo, TRANSPOSED to [n][k]
// ---------------------------------------------------------------------------
__global__ void convert_w_kernel(
    const float* __restrict__ wq, const float* __restrict__ wk,
    const float* __restrict__ wv, const float* __restrict__ ws)
{
    int m = blockIdx.y;
    const float* W = (m == 0) ? wq : (m == 1) ? wk : (m == 2) ? wv : ws;
    int idx = blockIdx.x * 256 + threadIdx.x;  // 0..16383
    int n = idx & 127, k = idx >> 7;
    float v = W[k * HC + n];
    __nv_bfloat16 hb = __float2bfloat16(v);
    __nv_bfloat16 lb = __float2bfloat16(v - __bfloat162float(hb));
    g_wh[m][n * INF + k] = __bfloat16_as_ushort(hb);
    g_wl[m][n * INF + k] = __bfloat16_as_ushort(lb);
}

// ---------------------------------------------------------------------------
// HMMA GEMM: D = x@W + b for 4 matrices, bf16 hi/lo split (3 terms).
// CTA = 128x128 tile, 8 warps (2x4), warp tile 64x32, m16n8k16 atoms.
// k and v results stored as fp16 for the edge-gather phase.
// ---------------------------------------------------------------------------
#define ASTRIDE 272          // bytes per smem row (136 bf16)
#define SM_A_H  0            // 128*272 = 34816
#define SM_A_L  34816
#define SM_B_H  69632
#define SM_B_L  104448
#define SM_BIAS 139264       // 512 floats = 2048
#define SM_TOT  141312

__global__ __launch_bounds__(256, 1) void mma_gemm_kernel(
    const float* __restrict__ bq, const float* __restrict__ bk,
    const float* __restrict__ bv, const float* __restrict__ bs,
    float* __restrict__ out)
{
    extern __shared__ char sm[];
    int tid = threadIdx.x;
    int w = tid >> 5;
    int lane = tid & 31;
    int g = lane >> 2;        // 0..7
    int t = lane & 3;         // 0..3
    int mw = w >> 2;          // 0..1
    int nw = w & 3;           // 0..3
    int rowBase = blockIdx.x * 128;

    #pragma unroll
    for (int i = 0; i < 8; i++) {
        int idx = tid + i * 256;          // 0..2047
        int r = idx >> 4;                 // row 0..127
        int kc = idx & 15;                // 8-bf16 chunk
        size_t src = ((size_t)(rowBase + r) * INF + kc * 8) * 2;
        *(uint4*)(sm + SM_A_H + r * ASTRIDE + kc * 16) =
            *(const uint4*)((const char*)g_xh + src);
        *(uint4*)(sm + SM_A_L + r * ASTRIDE + kc * 16) =
            *(const uint4*)((const char*)g_xl + src);
    }
    for (int j = tid; j < 512; j += 256) {
        int m = j >> 7, c = j & 127;
        const float* B = (m == 0) ? bq : (m == 1) ? bk : (m == 2) ? bv : bs;
        *(float*)(sm + SM_BIAS + j * 4) = B[c];
    }

    for (int m = 0; m < 4; m++) {
        __syncthreads();     // protect previous B from overwrite
        #pragma unroll
        for (int i = 0; i < 8; i++) {
            int idx = tid + i * 256;
            int n = idx >> 4;
            int kc = idx & 15;
            size_t src = ((size_t)n * INF + kc * 8) * 2;
            *(uint4*)(sm + SM_B_H + n * ASTRIDE + kc * 16) =
                *(const uint4*)((const char*)g_wh[m] + src);
            *(uint4*)(sm + SM_B_L + n * ASTRIDE + kc * 16) =
                *(const uint4*)((const char*)g_wl[m] + src);
        }
        __syncthreads();

        float acc[4][4][4];
        #pragma unroll
        for (int a = 0; a < 4; a++)
            #pragma unroll
            for (int b = 0; b < 4; b++)
                #pragma unroll
                for (int c = 0; c < 4; c++) acc[a][b][c] = 0.f;

        #pragma unroll
        for (int s = 0; s < 3; s++) {
            const char* Ab = sm + ((s == 2) ? SM_A_L : SM_A_H);
            const char* Bb = sm + ((s == 1) ? SM_B_L : SM_B_H);
            #pragma unroll
            for (int kt = 0; kt < 8; kt++) {
                int kb = (kt * 16 + t * 2) * 2;
                uint32_t bf[4][2];
                #pragma unroll
                for (int nt = 0; nt < 4; nt++) {
                    const char* p = Bb + (nw * 32 + nt * 8 + g) * ASTRIDE + kb;
                    bf[nt][0] = *(const uint32_t*)p;
                    bf[nt][1] = *(const uint32_t*)(p + 16);
                }
                #pragma unroll
                for (int mt = 0; mt < 4; mt++) {
                    const char* p = Ab + (mw * 64 + mt * 16 + g) * ASTRIDE + kb;
                    uint32_t a0 = *(const uint32_t*)p;
                    uint32_t a1 = *(const uint32_t*)(p + 8 * ASTRIDE);
                    uint32_t a2 = *(const uint32_t*)(p + 16);
                    uint32_t a3 = *(const uint32_t*)(p + 8 * ASTRIDE + 16);
                    #pragma unroll
                    for (int nt = 0; nt < 4; nt++) {
                        asm volatile(
                            "mma.sync.aligned.m16n8k16.row.col.f32.bf16.bf16.f32 "
                            "{%0,%1,%2,%3}, {%4,%5,%6,%7}, {%8,%9}, {%0,%1,%2,%3};"
                            : "+f"(acc[mt][nt][0]), "+f"(acc[mt][nt][1]),
                              "+f"(acc[mt][nt][2]), "+f"(acc[mt][nt][3])
                            : "r"(a0), "r"(a1), "r"(a2), "r"(a3),
                              "r"(bf[nt][0]), "r"(bf[nt][1]));
                    }
                }
            }
        }

        const float* sb = (const float*)(sm + SM_BIAS) + m * 128;
        if (m == 1 || m == 2) {
            __half* O = (m == 1) ? g_kh : g_vh;
            #pragma unroll
            for (int mt = 0; mt < 4; mt++) {
                int r0 = rowBase + mw * 64 + mt * 16 + g;
                int r1 = r0 + 8;
                #pragma unroll
                for (int nt = 0; nt < 4; nt++) {
                    int col = nw * 32 + nt * 8 + t * 2;
                    float bx = sb[col], by = sb[col + 1];
                    if (r0 < NN)
                        *(__half2*)&O[(size_t)r0 * HC + col] =
                            __floats2half2_rn(acc[mt][nt][0] + bx,
                                              acc[mt][nt][1] + by);
                    if (r1 < NN)
                        *(__half2*)&O[(size_t)r1 * HC + col] =
                            __floats2half2_rn(acc[mt][nt][2] + bx,
                                              acc[mt][nt][3] + by);
                }
            }
        } else {
            float* O = (m == 0) ? g_q : out;
            #pragma unroll
            for (int mt = 0; mt < 4; mt++) {
                int r0 = rowBase + mw * 64 + mt * 16 + g;
                int r1 = r0 + 8;
                #pragma unroll
                for (int nt = 0; nt < 4; nt++) {
                    int col = nw * 32 + nt * 8 + t * 2;
                    float bx = sb[col], by = sb[col + 1];
                    if (r0 < NN) {
                        float2 o0 = make_float2(acc[mt][nt][0] + bx,
                                                acc[mt][nt][1] + by);
                        *(float2*)&O[(size_t)r0 * HC + col] = o0;
                    }
                    if (r1 < NN) {
                        float2 o1 = make_float2(acc[mt][nt][2] + bx,
                                                acc[mt][nt][3] + by);
                        *(float2*)&O[(size_t)r1 * HC + col] = o1;
                    }
                }
            }
        }
    }
}

// ---------------------------------------------------------------------------
// FUSED edge kernel. CTA = 128 dst-sorted edges.
// Phase A: e = edge_attr[eid] @ w_e via HMMA (bf16 hi/lo, 3 terms), result
//          kept in SMEM as fp16 [128][128] — never touches global memory.
// Phase B: 8 warps x 16 sorted edges each: p = exp(q·(k+e)/4); run-length
//          accumulate num/den; red.global per dst-run boundary.
// ---------------------------------------------------------------------------
__global__ __launch_bounds__(256) void fused_edge_kernel(
    const float* __restrict__ ea, const float* __restrict__ we)
{
    __shared__ unsigned short Ah[FE_ROWS * 16], Al[FE_ROWS * 16];
    __shared__ unsigned short Bh[HC * 16], Bl[HC * 16];
    __shared__ __half Esm[FE_ROWS * HC];          // 32KB

    int tid = threadIdx.x;
    int e0 = blockIdx.x * FE_ROWS;                // EE % FE_ROWS == 0

    // ---- phase A load: gather ea rows by sorted eid -> bf16 hi/lo ----
    {
        int r = tid >> 1, half = (tid & 1) * 8;
        int eid = g_sde[e0 + r].z;
        float4 v0 = *(const float4*)&ea[(size_t)eid * ED + half];
        float4 v1 = *(const float4*)&ea[(size_t)eid * ED + half + 4];
        float vv[8] = {v0.x, v0.y, v0.z, v0.w, v1.x, v1.y, v1.z, v1.w};
        #pragma unroll
        for (int j = 0; j < 8; j++) {
            __nv_bfloat16 hb = __float2bfloat16(vv[j]);
            __nv_bfloat16 lb = __float2bfloat16(vv[j] - __bfloat162float(hb));
            Ah[r * 16 + half + j] = __bfloat16_as_ushort(hb);
            Al[r * 16 + half + j] = __bfloat16_as_ushort(lb);
        }
    }
    {
        int k = tid >> 4, n0 = (tid & 15) * 8;
        #pragma unroll
        for (int j = 0; j < 8; j++) {
            float v = we[k * HC + n0 + j];
            __nv_bfloat16 hb = __float2bfloat16(v);
            __nv_bfloat16 lb = __float2bfloat16(v - __bfloat162float(hb));
            Bh[(n0 + j) * 16 + k] = __bfloat16_as_ushort(hb);
            Bl[(n0 + j) * 16 + k] = __bfloat16_as_ushort(lb);
        }
    }
    __syncthreads();

    int w = tid >> 5, lane = tid & 31;
    int g = lane >> 2, t = lane & 3;
    int mw = w >> 1, nw = w & 1;

    // ---- phase A MMA: warp tile 32 rows x 64 cols ----
    {
        float acc[2][8][4];
        #pragma unroll
        for (int a = 0; a < 2; a++)
            #pragma unroll
            for (int b = 0; b < 8; b++)
                #pragma unroll
                for (int c = 0; c < 4; c++) acc[a][b][c] = 0.f;

        #pragma unroll
        for (int s = 0; s < 3; s++) {
            const unsigned short* A = (s == 2) ? Al : Ah;
            const unsigned short* B = (s == 1) ? Bl : Bh;
            uint32_t bf[8][2];
            #pragma unroll
            for (int nt = 0; nt < 8; nt++) {
                const unsigned short* p = &B[(nw * 64 + nt * 8 + g) * 16 + t * 2];
                bf[nt][0] = *(const uint32_t*)p;
                bf[nt][1] = *(const uint32_t*)(p + 8);
            }
            #pragma unroll
            for (int mt = 0; mt < 2; mt++) {
                const unsigned short* p = &A[(mw * 32 + mt * 16 + g) * 16 + t * 2];
                uint32_t a0 = *(const uint32_t*)p;
                uint32_t a1 = *(const uint32_t*)(p + 8 * 16);
                uint32_t a2 = *(const uint32_t*)(p + 8);
                uint32_t a3 = *(const uint32_t*)(p + 8 * 16 + 8);
                #pragma unroll
                for (int nt = 0; nt < 8; nt++) {
                    asm volatile(
                        "mma.sync.aligned.m16n8k16.row.col.f32.bf16.bf16.f32 "
                        "{%0,%1,%2,%3}, {%4,%5,%6,%7}, {%8,%9}, {%0,%1,%2,%3};"
                        : "+f"(acc[mt][nt][0]), "+f"(acc[mt][nt][1]),
                          "+f"(acc[mt][nt][2]), "+f"(acc[mt][nt][3])
                        : "r"(a0), "r"(a1), "r"(a2), "r"(a3),
                          "r"(bf[nt][0]), "r"(bf[nt][1]));
                }
            }
        }

        // epilogue: fragments -> Esm fp16
        #pragma unroll
        for (int mt = 0; mt < 2; mt++) {
            int r0 = mw * 32 + mt * 16 + g;
            int r1 = r0 + 8;
            #pragma unroll
            for (int nt = 0; nt < 8; nt++) {
                int col = nw * 64 + nt * 8 + t * 2;
                *(__half2*)&Esm[r0 * HC + col] =
                    __floats2half2_rn(acc[mt][nt][0], acc[mt][nt][1]);
                *(__half2*)&Esm[r1 * HC + col] =
                    __floats2half2_rn(acc[mt][nt][2], acc[mt][nt][3]);
            }
        }
    }
    __syncthreads();

    // ---- phase B: 16 sorted edges per warp, e from SMEM ----
    int c0 = lane << 2;
    int head = lane >> 2;
    int lbase = w * 16;                 // local row in Esm
    int gbase = e0 + lbase;             // global sorted position

    int cur_dst = -1;
    float4 q4 = make_float4(0.f, 0.f, 0.f, 0.f);
    float nx = 0.f, ny = 0.f, nz = 0.f, nw4 = 0.f, den = 0.f;

    #pragma unroll 4
    for (int i = 0; i < 16; i++) {
        int4 sde = g_sde[gbase + i];
        int src = sde.x, dst = sde.y;

        if (dst != cur_dst) {
            if (cur_dst >= 0) {
                float* op = g_attn + (size_t)cur_dst * HC + c0;
                asm volatile("red.global.add.v4.f32 [%0], {%1, %2, %3, %4};"
                             :: "l"(op), "f"(nx), "f"(ny), "f"(nz), "f"(nw4)
                             : "memory");
                if ((lane & 3) == 0) {
                    float* dp = &g_sum[cur_dst * HH + head];
                    asm volatile("red.global.add.f32 [%0], %1;"
                                 :: "l"(dp), "f"(den) : "memory");
                }
            }
            cur_dst = dst;
            q4 = *(const float4*)&g_q[(size_t)dst * HC + c0];
            nx = ny = nz = nw4 = den = 0.f;
        }

        uint2 eu = *(const uint2*)&Esm[(lbase + i) * HC + c0];
        float2 e01 = __half22float2(*reinterpret_cast<__half2*>(&eu.x));
        float2 e23 = __half22float2(*reinterpret_cast<__half2*>(&eu.y));

        uint2 ku = *(const uint2*)&g_kh[(size_t)src * HC + c0];
        float2 k01 = __half22float2(*reinterpret_cast<__half2*>(&ku.x));
        float2 k23 = __half22float2(*reinterpret_cast<__half2*>(&ku.y));

        float s = q4.x * (k01.x + e01.x) + q4.y * (k01.y + e01.y)
                + q4.z * (k23.x + e23.x) + q4.w * (k23.y + e23.y);
        s += __shfl_xor_sync(0xffffffffu, s, 1);
        s += __shfl_xor_sync(0xffffffffu, s, 2);

        float p = __expf(s * 0.25f);

        uint2 vu = *(const uint2*)&g_vh[(size_t)src * HC + c0];
        float2 v01 = __half22float2(*reinterpret_cast<__half2*>(&vu.x));
        float2 v23 = __half22float2(*reinterpret_cast<__half2*>(&vu.y));

        nx  += (v01.x + e01.x) * p;
        ny  += (v01.y + e01.y) * p;
        nz  += (v23.x + e23.x) * p;
        nw4 += (v23.y + e23.y) * p;
        den += p;
    }

    if (cur_dst >= 0) {
        float* op = g_attn + (size_t)cur_dst * HC + c0;
        asm volatile("red.global.add.v4.f32 [%0], {%1, %2, %3, %4};"
                     :: "l"(op), "f"(nx), "f"(ny), "f"(nz), "f"(nw4)
                     : "memory");
        if ((lane & 3) == 0) {
            float* dp = &g_sum[cur_dst * HH + head];
            asm volatile("red.global.add.f32 [%0], %1;"
                         :: "l"(dp), "f"(den) : "memory");
        }
    }
}

// ---------------------------------------------------------------------------
__global__ __launch_bounds__(256) void normalize_kernel(float* __restrict__ out)
{
    int i = blockIdx.x * blockDim.x + threadIdx.x;
    int n4 = (NN * HC) / 4;
    if (i >= n4) return;
    int node = i >> 5;
    int head = (i & 31) >> 2;
    float inv = 1.f / (g_sum[node * HH + head] + 1e-16f);
    float4 a = ((const float4*)g_attn)[i];
    float4 o = ((float4*)out)[i];
    o.x += a.x * inv; o.y += a.y * inv;
    o.z += a.z * inv; o.w += a.w * inv;
    ((float4*)out)[i] = o;
}

// ---------------------------------------------------------------------------
extern "C" void kernel_launch(void* const* d_in, const int* in_sizes, int n_in,
                              void* d_out, int out_size)
{
    const float* x  = (const float*)d_in[0];
    const int*   ei = (const int*)d_in[1];
    const float* ea = (const float*)d_in[2];
    const float* wq = (const float*)d_in[3];
    const float* bq = (const float*)d_in[4];
    const float* wk = (const float*)d_in[5];
    const float* bk = (const float*)d_in[6];
    const float* wv = (const float*)d_in[7];
    const float* bv = (const float*)d_in[8];
    const float* we = (const float*)d_in[9];
    const float* ws = (const float*)d_in[10];
    const float* bs = (const float*)d_in[11];
    float* out = (float*)d_out;

    static bool attr_set = false;
    if (!attr_set) {
        cudaFuncSetAttribute(mma_gemm_kernel,
                             cudaFuncAttributeMaxDynamicSharedMemorySize, SM_TOT);
        attr_set = true;
    }

    // 4th launch = ncu's captured slot -> mma_gemm
    zero_kernel<<<((NN * HC) / 4 + 255) / 256, 256>>>();
    convert_x_kernel<<<((NN * INF) / 4 + 255) / 256, 256>>>(x);
    dim3 gw(64, 4);
    convert_w_kernel<<<gw, 256>>>(wq, wk, wv, ws);
    mma_gemm_kernel<<<391, 256, SM_TOT>>>(bq, bk, bv, bs, out);   // 4th: profiled

    hist_kernel<<<(EE + 255) / 256, 256>>>(ei);
    scan1_kernel<<<196, 256>>>();
    scan2_kernel<<<1, 256>>>();
    scan3_kernel<<<NPAD / 256, 256>>>();
    permute_kernel<<<(EE + 255) / 256, 256>>>(ei);

    fused_edge_kernel<<<EE / FE_ROWS, 256>>>(ea, we);

    normalize_kernel<<<((NN * HC) / 4 + 255) / 256, 256>>>(out);
}